// round 16
// baseline (speedup 1.0000x reference)
#include <cuda_runtime.h>
#include <stdint.h>

// ---------------- problem constants ----------------
#define B_   8
#define F_   64
#define E_   50000
#define CO_  128
#define KK_  320
#define UE_  64          // edges per pipeline unit (MMA N)
#define NT_  512         // threads per CTA (16 warps)
#define UPB_ 782         // ceil(50000/64): units AND transpose tiles per batch
#define NSTEP_ 40        // 320 / 8 (tf32 K per MMA)

#define TMEM_A_  128     // A: cols 128..447; D buffers: 0, 64, 448
#define WS_STR_  324
#define HDR_     4096
#define BUF_     81920   // one G buffer
#define EP_OFF_  (HDR_ + 2 * BUF_)           // 167936
#define EP_STR_  68
#define TS_OFF_  (EP_OFF_ + CO_ * EP_STR_ * 4)   // 202752: transpose tile buf
#define SMEM_SZ_ (TS_OFF_ + 64 * 68 * 4)         // 220160 B

// idesc kind::tf32: c=F32, a=TF32, b=TF32, N=64, M=128
#define IDESC64_ 0x8100910u

__device__ __align__(16) float g_xt[(size_t)B_ * E_ * F_];
__device__ int g_idx64;
__device__ int g_td[B_ + 1];     // tiles-done counter per batch

#if defined(__CUDA_ARCH_FEAT_SM103_ALL)
#define TC_OK_ 1
#else
#define TC_OK_ 0
#endif

// ---------------- PTX helpers (generic) ----------------
__device__ __forceinline__ uint32_t smem_u32(const void* p) {
    uint32_t a;
    asm("{ .reg .u64 t; cvta.to.shared.u64 t, %1; cvt.u32.u64 %0, t; }" : "=r"(a) : "l"(p));
    return a;
}
__device__ __forceinline__ uint32_t elect1() {
    uint32_t p;
    asm volatile("{ .reg .pred p; elect.sync _|p, 0xFFFFFFFF; selp.b32 %0, 1, 0, p; }" : "=r"(p));
    return p;
}
__device__ __forceinline__ float f2t(float x) {
    uint32_t u;
    asm("cvt.rna.tf32.f32 %0, %1;" : "=r"(u) : "f"(x));
    return __uint_as_float(u);
}

#define MB_INIT(mb, c)    asm volatile("mbarrier.init.shared.b64 [%0], %1;" :: "r"(mb), "r"(c) : "memory")
#define MB_INVAL(mb)      asm volatile("mbarrier.inval.shared.b64 [%0];" :: "r"(mb) : "memory")

#define MB_WAIT_PARITY(mb, ph) do {                                          \
    uint32_t _m = (mb), _p = (ph), _d;                                       \
    asm volatile("{ .reg .pred p; mbarrier.try_wait.parity.acquire.cta.shared::cta.b64 p, [%1], %2; selp.b32 %0,1,0,p; }" \
                 : "=r"(_d) : "r"(_m), "r"(_p) : "memory");                  \
    if (!_d) {                                                               \
        asm volatile("{ .reg .pred P1;\n"                                    \
            "WL_%=: mbarrier.try_wait.parity.acquire.cta.shared::cta.b64 P1, [%0], %1, 0x989680;\n" \
            "@P1 bra.uni WD_%=;\n bra.uni WL_%=;\nWD_%=: }"                  \
            :: "r"(_m), "r"(_p) : "memory");                                 \
    } } while (0)

// ---------------- tcgen05 helpers (sm_103a-only) ----------------
#if TC_OK_
#define TC_ALLOC(sa, n)   asm volatile("tcgen05.alloc.cta_group::1.sync.aligned.shared::cta.b32 [%0], %1;" :: "r"(sa), "r"(n) : "memory")
#define TC_RELINQ()       asm volatile("tcgen05.relinquish_alloc_permit.cta_group::1.sync.aligned;")
#define TC_DEALLOC(t, n)  asm volatile("tcgen05.dealloc.cta_group::1.sync.aligned.b32 %0, %1;" :: "r"(t), "r"(n))
#define TC_WAIT_ST()      asm volatile("tcgen05.wait::st.sync.aligned;" ::: "memory")
#define TC_WAIT_LD()      asm volatile("tcgen05.wait::ld.sync.aligned;" ::: "memory")
#define TC_FENCE_BEFORE() asm volatile("tcgen05.fence::before_thread_sync;" ::: "memory")
#define TC_FENCE_AFTER()  asm volatile("tcgen05.fence::after_thread_sync;" ::: "memory")
#define TC_COMMIT(mb)     asm volatile("tcgen05.commit.cta_group::1.mbarrier::arrive::one.shared::cluster.b64 [%0];" :: "r"(mb) : "memory")

#define TC_ST_X32(addr, r) \
    asm volatile("tcgen05.st.sync.aligned.32x32b.x32.b32 [%0], "             \
        "{%1,%2,%3,%4,%5,%6,%7,%8,%9,%10,%11,%12,%13,%14,%15,%16,"          \
        "%17,%18,%19,%20,%21,%22,%23,%24,%25,%26,%27,%28,%29,%30,%31,%32};" \
        :: "r"(addr),                                                        \
        "r"((r)[0]),"r"((r)[1]),"r"((r)[2]),"r"((r)[3]),"r"((r)[4]),"r"((r)[5]),"r"((r)[6]),"r"((r)[7]), \
        "r"((r)[8]),"r"((r)[9]),"r"((r)[10]),"r"((r)[11]),"r"((r)[12]),"r"((r)[13]),"r"((r)[14]),"r"((r)[15]), \
        "r"((r)[16]),"r"((r)[17]),"r"((r)[18]),"r"((r)[19]),"r"((r)[20]),"r"((r)[21]),"r"((r)[22]),"r"((r)[23]), \
        "r"((r)[24]),"r"((r)[25]),"r"((r)[26]),"r"((r)[27]),"r"((r)[28]),"r"((r)[29]),"r"((r)[30]),"r"((r)[31]) \
        : "memory")

#define TC_LD_X16(r, addr) \
    asm volatile("tcgen05.ld.sync.aligned.32x32b.x16.b32 "                   \
        "{%0,%1,%2,%3,%4,%5,%6,%7,%8,%9,%10,%11,%12,%13,%14,%15}, [%16];"    \
        : "=r"((r)[0]),"=r"((r)[1]),"=r"((r)[2]),"=r"((r)[3]),               \
        "=r"((r)[4]),"=r"((r)[5]),"=r"((r)[6]),"=r"((r)[7]),                 \
        "=r"((r)[8]),"=r"((r)[9]),"=r"((r)[10]),"=r"((r)[11]),               \
        "=r"((r)[12]),"=r"((r)[13]),"=r"((r)[14]),"=r"((r)[15])              \
        : "r"(addr))

__device__ __forceinline__ void mma_tf32_ts(uint32_t d, uint32_t a, uint64_t bdesc,
                                            uint32_t idesc, bool acc) {
    uint32_t en = acc ? 1u : 0u;
    asm volatile(
        "{\n\t.reg .pred p;\n\tsetp.ne.u32 p, %5, 0;\n\t"
        "tcgen05.mma.cta_group::1.kind::tf32 [%0], [%1], %2, %3, {%4, %4, %4, %4}, p;\n\t}"
        :: "r"(d), "r"(a), "l"(bdesc), "r"(idesc), "r"(0u), "r"(en) : "memory");
}
#endif // TC_OK_

#define DESC_BASE_ ((2ull << 61) | (1ull << 46) | (64ull << 32) | (1ull << 16))
#define MAKE_DESC(a) (DESC_BASE_ | ((uint64_t)((a) >> 4) & 0x3FFF))
#define SWZ(o) ((o) ^ (((o) >> 3) & 0x70))

// ---------------------------------------------------------------------------
// Reset + dtype detect kernel (runs first, stream-ordered)
// ---------------------------------------------------------------------------
__global__ void reset_kernel(const unsigned int* __restrict__ g) {
    __shared__ int s_nz;
    int tid = threadIdx.x;
    if (tid <= B_) g_td[tid] = 0;
    if (tid == 0) s_nz = 0;
    __syncthreads();
    unsigned acc = 0;
    #pragma unroll
    for (int i = 0; i < 8; i++) acc |= g[(tid + i * 256) * 2 + 1];
    if (acc) atomicOr(&s_nz, 1);
    __syncthreads();
    if (tid == 0) g_idx64 = (s_nz == 0) ? 1 : 0;
}

// ---------------------------------------------------------------------------
// Fused persistent kernel: transpose(b+1) interleaved with units(b).
// ---------------------------------------------------------------------------
__global__ __launch_bounds__(NT_, 1)
void meshconv_fused(const float* __restrict__ x,
                    const void*  __restrict__ gemm_raw,
                    const float* __restrict__ Wg,
                    const float* __restrict__ bias,
                    float*       __restrict__ out)
{
#if TC_OK_
    extern __shared__ char smem[];
    uint32_t sbase = smem_u32(smem);
    char*  tile = smem + HDR_;
    float* ep   = (float*)(smem + EP_OFF_);
    float* ts   = (float*)(smem + TS_OFF_);
    uint32_t gsb = sbase + HDR_;

    const int tid = threadIdx.x, wid = tid >> 5, lane = tid & 31;
    const int idx64 = g_idx64;
    const int gdim  = (int)gridDim.x;
    const int R     = UPB_ % gdim;

    if (wid == 0) {
        TC_ALLOC(sbase, 512);
        TC_RELINQ();
        if (elect1()) {
            MB_INIT(sbase + 8, 1); MB_INIT(sbase + 16, 1); MB_INIT(sbase + 24, 1);
        }
    }
    __syncthreads();
    uint32_t tmem;
    asm volatile("ld.shared.b32 %0, [%1];" : "=r"(tmem) : "r"(sbase));

    // ---- stage W: gmem -> smem (kappa = f*5+q -> kappa' = q*64+f) ----
    float* ws = (float*)tile;
    #pragma unroll 4
    for (int i = 0; i < 20; i++) {
        int idx4 = tid + i * NT_;
        int o = idx4 / 80, c4 = idx4 % 80;
        float4 v = *(const float4*)(Wg + o * KK_ + c4 * 4);
        int kk = c4 * 4;
        ws[o * WS_STR_ + ((kk    ) % 5) * 64 + (kk    ) / 5] = v.x;
        ws[o * WS_STR_ + ((kk + 1) % 5) * 64 + (kk + 1) / 5] = v.y;
        ws[o * WS_STR_ + ((kk + 2) % 5) * 64 + (kk + 2) / 5] = v.z;
        ws[o * WS_STR_ + ((kk + 3) % 5) * 64 + (kk + 3) / 5] = v.w;
    }
    __syncthreads();

    // ---- smem -> TMEM (A operand, tf32) ----
    if (tid < 128) {
        const float* wrow = ws + tid * WS_STR_;
        uint32_t woff = (uint32_t)(wid & 3) << 21;
        for (int g = 0; g < 10; g++) {
            uint32_t r[32];
            #pragma unroll
            for (int u = 0; u < 8; u++) {
                float4 v = *(const float4*)(wrow + g * 32 + u * 4);
                asm("cvt.rna.tf32.f32 %0, %1;" : "=r"(r[u*4+0]) : "f"(v.x));
                asm("cvt.rna.tf32.f32 %0, %1;" : "=r"(r[u*4+1]) : "f"(v.y));
                asm("cvt.rna.tf32.f32 %0, %1;" : "=r"(r[u*4+2]) : "f"(v.z));
                asm("cvt.rna.tf32.f32 %0, %1;" : "=r"(r[u*4+3]) : "f"(v.w));
            }
            TC_ST_X32(tmem + TMEM_A_ + g * 32 + woff, r);
            TC_WAIT_ST();
        }
    }
    TC_FENCE_BEFORE();
    __syncthreads();

    // ---- per-thread constants ----
    const int c    = tid & 15;
    const int eA   = tid >> 4;               // edge within sub-unit (0..31)
    const int half = c >> 3, i4 = c & 7;
    const uint32_t swzA = SWZ(((uint32_t)(eA >> 3) << 10) + ((uint32_t)(eA & 7) << 7) + ((uint32_t)i4 << 4));
    const int eB   = eA + 32;
    const uint32_t swzB = SWZ(((uint32_t)(eB >> 3) << 10) + ((uint32_t)(eB & 7) << 7) + ((uint32_t)i4 << 4));
    const int g16  = wid >> 2;
    const int orow = (wid & 3) * 32 + lane;
    const float bv = __ldg(bias + orow);
    float* eprow   = ep + orow * EP_STR_ + g16 * 16;
    // transpose-tile thread mapping
    const int tf  = tid >> 4;                // load: feature row pair base (s*... below)
    const int tc4 = tid & 15;                // load: float4 col within tile

    // ---- prologue: transpose tiles of batch 0 (blob) ----
    {
        int vcT0 = (int)(blockIdx.x % (unsigned)gdim);
        int myT0 = (UPB_ - 1 - vcT0) / gdim + 1;
        for (int k = 0; k < myT0; k++) {
            int te0 = (vcT0 + k * gdim) * 64;
            float4 tv[2];
            #pragma unroll
            for (int s = 0; s < 2; s++) {
                int f = tf + s * 32;
                if (te0 + 64 <= E_) {
                    tv[s] = *(const float4*)(x + (size_t)f * E_ + te0 + tc4 * 4);
                } else {
                    float q[4];
                    #pragma unroll
                    for (int qq = 0; qq < 4; qq++) {
                        int ge = te0 + tc4 * 4 + qq;
                        q[qq] = (ge < E_) ? x[(size_t)f * E_ + ge] : 0.f;
                    }
                    tv[s] = make_float4(q[0], q[1], q[2], q[3]);
                }
            }
            #pragma unroll
            for (int s = 0; s < 2; s++)
                *(float4*)(ts + (tf + s * 32) * 68 + tc4 * 4) = tv[s];
            __syncthreads();
            #pragma unroll
            for (int s = 0; s < 2; s++) {
                int oidx = tid + s * NT_;
                int j16 = oidx >> 6, e = oidx & 63;
                float4 w = make_float4(ts[(j16*4+0)*68 + e], ts[(j16*4+1)*68 + e],
                                       ts[(j16*4+2)*68 + e], ts[(j16*4+3)*68 + e]);
                int ge = te0 + e;
                if (ge < E_) *(float4*)(g_xt + (size_t)ge * F_ + j16 * 4) = w;
            }
            __syncthreads();
        }
        __threadfence();
        __syncthreads();
        if (tid == 0) atomicAdd(&g_td[0], myT0);
    }

    // ---- batch loop ----
    int i = 0; int pb2[2], pe2[2];
    for (int b = 0; b < B_; b++) {
        int vcU = (int)((blockIdx.x + (unsigned)(b * R)) % (unsigned)gdim);
        int myU = (UPB_ - 1 - vcU) / gdim + 1;
        int tb = b + 1;
        int vcT = 0, myT = 0;
        if (tb < B_) {
            vcT = (int)((blockIdx.x + (unsigned)(tb * R)) % (unsigned)gdim);
            myT = (UPB_ - 1 - vcT) / gdim + 1;
        }

        // wait for xt of batch b
        if (tid == 0) {
            volatile int* pf = &g_td[b];
            while (*pf < UPB_) __nanosleep(128);
        }
        __syncthreads();
        __threadfence();

        int jmax = myU;
        if (myT > 0 && myT + 1 > jmax) jmax = myT + 1;

        const float* xb = g_xt + (size_t)b * E_ * F_;
        int cur_eg[2], cur_n[2][4];
        bool have = false;
        float4 tva, tvb; int pte0 = 0;

        for (int j = 0; j < jmax; j++) {
            bool dou = (j < myU);
            bool dtl = (j < myT);
            bool dts = (j >= 1) && (j - 1 < myT);
            int e0 = (vcU + j * gdim) * UE_;

            // ======== Phase A ========
            float4 v[2][5];
            if (dou) {
                if (!have) {
                    #pragma unroll
                    for (int ii = 0; ii < 2; ii++) {
                        int eg = e0 + eA + ii * 32; if (eg > E_ - 1) eg = E_ - 1;
                        cur_eg[ii] = eg;
                        if (idx64) {
                            const long long* gp = (const long long*)gemm_raw + ((size_t)b * E_ + eg) * 4;
                            cur_n[ii][0]=(int)gp[0]; cur_n[ii][1]=(int)gp[1]; cur_n[ii][2]=(int)gp[2]; cur_n[ii][3]=(int)gp[3];
                        } else {
                            int4 gi = *(const int4*)((const int*)gemm_raw + ((size_t)b * E_ + eg) * 4);
                            cur_n[ii][0]=gi.x; cur_n[ii][1]=gi.y; cur_n[ii][2]=gi.z; cur_n[ii][3]=gi.w;
                        }
                    }
                }
                #pragma unroll
                for (int ii = 0; ii < 2; ii++) {
                    v[ii][0] = *((const float4*)(xb + (size_t)cur_eg[ii]   * F_) + c);
                    v[ii][1] = *((const float4*)(xb + (size_t)cur_n[ii][0] * F_) + c);
                    v[ii][2] = *((const float4*)(xb + (size_t)cur_n[ii][1] * F_) + c);
                    v[ii][3] = *((const float4*)(xb + (size_t)cur_n[ii][2] * F_) + c);
                    v[ii][4] = *((const float4*)(xb + (size_t)cur_n[ii][3] * F_) + c);
                }
            }
            // prefetch next unit's indices (within batch)
            int nxt_eg[2], nxt_n[2][4];
            bool nhave = false;
            if (dou && (j + 1 < myU)) {
                int ne0 = (vcU + (j + 1) * gdim) * UE_;
                #pragma unroll
                for (int ii = 0; ii < 2; ii++) {
                    int eg = ne0 + eA + ii * 32; if (eg > E_ - 1) eg = E_ - 1;
                    nxt_eg[ii] = eg;
                    if (idx64) {
                        const long long* gp = (const long long*)gemm_raw + ((size_t)b * E_ + eg) * 4;
                        nxt_n[ii][0]=(int)gp[0]; nxt_n[ii][1]=(int)gp[1]; nxt_n[ii][2]=(int)gp[2]; nxt_n[ii][3]=(int)gp[3];
                    } else {
                        int4 gi = *(const int4*)((const int*)gemm_raw + ((size_t)b * E_ + eg) * 4);
                        nxt_n[ii][0]=gi.x; nxt_n[ii][1]=gi.y; nxt_n[ii][2]=gi.z; nxt_n[ii][3]=gi.w;
                    }
                }
                nhave = true;
            }
            // write out transposed tile j-1 to xt[tb]
            if (dts) {
                float* xto = g_xt + (size_t)tb * E_ * F_;
                #pragma unroll
                for (int s = 0; s < 2; s++) {
                    int oidx = tid + s * NT_;
                    int j16 = oidx >> 6, e = oidx & 63;
                    float4 w = make_float4(ts[(j16*4+0)*68 + e], ts[(j16*4+1)*68 + e],
                                           ts[(j16*4+2)*68 + e], ts[(j16*4+3)*68 + e]);
                    int ge = pte0 + e;
                    if (ge < E_) *(float4*)(xto + (size_t)ge * F_ + j16 * 4) = w;
                }
                __threadfence();
            }
            // load tile j of batch tb
            if (dtl) {
                int te0 = (vcT + j * gdim) * 64;
                const float* xsrc = x + (size_t)tb * F_ * E_;
                if (te0 + 64 <= E_) {
                    tva = *(const float4*)(xsrc + (size_t)tf        * E_ + te0 + tc4 * 4);
                    tvb = *(const float4*)(xsrc + (size_t)(tf + 32) * E_ + te0 + tc4 * 4);
                } else {
                    float qa[4], qb[4];
                    #pragma unroll
                    for (int qq = 0; qq < 4; qq++) {
                        int ge = te0 + tc4 * 4 + qq;
                        qa[qq] = (ge < E_) ? xsrc[(size_t)tf        * E_ + ge] : 0.f;
                        qb[qq] = (ge < E_) ? xsrc[(size_t)(tf + 32) * E_ + ge] : 0.f;
                    }
                    tva = make_float4(qa[0], qa[1], qa[2], qa[3]);
                    tvb = make_float4(qb[0], qb[1], qb[2], qb[3]);
                }
                pte0 = te0;
            }
            // epilogue part 1 for unit i-2
            if (dou && i >= 2) {
                int jj = i - 2, s = jj % 3;
                MB_WAIT_PARITY(sbase + 8 + s * 8, (jj / 3) & 1);
                TC_FENCE_AFTER();
                uint32_t doff = (s == 0) ? 0u : (s == 1) ? 64u : 448u;
                uint32_t r[16];
                TC_LD_X16(r, tmem + doff + g16 * 16);
                TC_WAIT_LD();
                #pragma unroll
                for (int q = 0; q < 4; q++) {
                    float4 w = make_float4(__uint_as_float(r[4*q+0]) + bv,
                                           __uint_as_float(r[4*q+1]) + bv,
                                           __uint_as_float(r[4*q+2]) + bv,
                                           __uint_as_float(r[4*q+3]) + bv);
                    *(float4*)(eprow + 4 * q) = w;
                }
            }
            __syncthreads();

            // ======== Phase B ========
            if (dts && tid == 0) atomicAdd(&g_td[tb], 1);
            if (dou && i >= 2) {
                int jb2 = pb2[i & 1], je0 = pe2[i & 1];
                #pragma unroll
                for (int j4 = 0; j4 < 4; j4++) {
                    int idx = tid + j4 * NT_;
                    int row = idx >> 4, c4 = idx & 15;
                    float4 w = *(const float4*)(ep + row * EP_STR_ + c4 * 4);
                    int e = je0 + c4 * 4;
                    float* po = out + ((size_t)jb2 * CO_ + row) * E_ + e;
                    if (e + 3 < E_) {
                        *(float4*)po = w;
                    } else {
                        if (e + 0 < E_) po[0] = w.x;
                        if (e + 1 < E_) po[1] = w.y;
                        if (e + 2 < E_) po[2] = w.z;
                        if (e + 3 < E_) po[3] = w.w;
                    }
                }
            }
            if (dou) {
                char* buf = tile + (i & 1) * BUF_;
                #pragma unroll
                for (int ii = 0; ii < 2; ii++) {
                    float4 v0 = v[ii][0], v1 = v[ii][1], v2 = v[ii][2], v3 = v[ii][3], v4 = v[ii][4];
                    float4 w0 = make_float4(f2t(v0.x), f2t(v0.y), f2t(v0.z), f2t(v0.w));
                    float4 w1 = make_float4(f2t(v1.x+v3.x), f2t(v1.y+v3.y), f2t(v1.z+v3.z), f2t(v1.w+v3.w));
                    float4 w2 = make_float4(f2t(v2.x+v4.x), f2t(v2.y+v4.y), f2t(v2.z+v4.z), f2t(v2.w+v4.w));
                    float4 w3 = make_float4(f2t(fabsf(v1.x-v3.x)), f2t(fabsf(v1.y-v3.y)),
                                            f2t(fabsf(v1.z-v3.z)), f2t(fabsf(v1.w-v3.w)));
                    float4 w4 = make_float4(f2t(fabsf(v2.x-v4.x)), f2t(fabsf(v2.y-v4.y)),
                                            f2t(fabsf(v2.z-v4.z)), f2t(fabsf(v2.w-v4.w)));
                    uint32_t sb = ii ? swzB : swzA;
                    *(float4*)(buf + sb + (uint32_t)((0 + half) << 13)) = w0;
                    *(float4*)(buf + sb + (uint32_t)((2 + half) << 13)) = w1;
                    *(float4*)(buf + sb + (uint32_t)((4 + half) << 13)) = w2;
                    *(float4*)(buf + sb + (uint32_t)((6 + half) << 13)) = w3;
                    *(float4*)(buf + sb + (uint32_t)((8 + half) << 13)) = w4;
                }
            }
            if (dtl) {
                *(float4*)(ts + tf        * 68 + tc4 * 4) = tva;
                *(float4*)(ts + (tf + 32) * 68 + tc4 * 4) = tvb;
            }
            asm volatile("fence.proxy.async.shared::cta;" ::: "memory");
            __syncthreads();

            if (dou) {
                if (wid == 0) {
                    TC_FENCE_AFTER();
                    if (elect1()) {
                        int s = i % 3;
                        uint32_t doff = (s == 0) ? 0u : (s == 1) ? 64u : 448u;
                        uint64_t bb = MAKE_DESC(gsb + (uint32_t)(i & 1) * BUF_);
                        #pragma unroll 1
                        for (int k = 0; k < NSTEP_; k++) {
                            uint64_t bd = bb + (uint64_t)((k >> 2) * 512 + (k & 3) * 2);
                            mma_tf32_ts(tmem + doff, tmem + TMEM_A_ + k * 8, bd, IDESC64_, k > 0);
                        }
                        TC_COMMIT(sbase + 8 + s * 8);
                    }
                }
                pb2[i & 1] = b; pe2[i & 1] = e0;
                #pragma unroll
                for (int ii = 0; ii < 2; ii++) {
                    cur_eg[ii] = nxt_eg[ii];
                    cur_n[ii][0]=nxt_n[ii][0]; cur_n[ii][1]=nxt_n[ii][1];
                    cur_n[ii][2]=nxt_n[ii][2]; cur_n[ii][3]=nxt_n[ii][3];
                }
                have = nhave;
                i++;
            }
        }
    }

    // ---- drain: epilogues for the last two units ----
    for (int j = i - 2; j < i; j++) {
        if (j < 0) continue;
        int s = j % 3;
        MB_WAIT_PARITY(sbase + 8 + s * 8, (j / 3) & 1);
        TC_FENCE_AFTER();
        uint32_t doff = (s == 0) ? 0u : (s == 1) ? 64u : 448u;
        uint32_t r[16];
        TC_LD_X16(r, tmem + doff + g16 * 16);
        TC_WAIT_LD();
        #pragma unroll
        for (int q = 0; q < 4; q++) {
            float4 w = make_float4(__uint_as_float(r[4*q+0]) + bv,
                                   __uint_as_float(r[4*q+1]) + bv,
                                   __uint_as_float(r[4*q+2]) + bv,
                                   __uint_as_float(r[4*q+3]) + bv);
            *(float4*)(eprow + 4 * q) = w;
        }
        __syncthreads();
        int jb2 = pb2[j & 1], je0 = pe2[j & 1];
        #pragma unroll
        for (int j4 = 0; j4 < 4; j4++) {
            int idx = tid + j4 * NT_;
            int row = idx >> 4, c4 = idx & 15;
            float4 w = *(const float4*)(ep + row * EP_STR_ + c4 * 4);
            int e = je0 + c4 * 4;
            float* po = out + ((size_t)jb2 * CO_ + row) * E_ + e;
            if (e + 3 < E_) {
                *(float4*)po = w;
            } else {
                if (e + 0 < E_) po[0] = w.x;
                if (e + 1 < E_) po[1] = w.y;
                if (e + 2 < E_) po[2] = w.z;
                if (e + 3 < E_) po[3] = w.w;
            }
        }
        __syncthreads();
    }

    // ---- cleanup ----
    __syncthreads();
    if (wid == 0) {
        if (elect1()) {
            MB_INVAL(sbase + 8); MB_INVAL(sbase + 16); MB_INVAL(sbase + 24);
        }
        TC_DEALLOC(tmem, 512);
    }
#endif // TC_OK_
}

// ---------------------------------------------------------------------------
extern "C" void kernel_launch(void* const* d_in, const int* in_sizes, int n_in,
                              void* d_out, int out_size) {
    const float* x    = (const float*)d_in[0];
    const void*  gemm = d_in[1];
    const float* W    = (const float*)d_in[2];
    const float* bias = (const float*)d_in[3];
    float*       out  = (float*)d_out;

    reset_kernel<<<1, 256>>>((const unsigned int*)gemm);

    int dev = 0, nsm = 148;
    cudaGetDevice(&dev);
    cudaDeviceGetAttribute(&nsm, cudaDevAttrMultiProcessorCount, dev);
    if (nsm <= 0) nsm = 148;

    cudaFuncSetAttribute(meshconv_fused,
                         cudaFuncAttributeMaxDynamicSharedMemorySize, SMEM_SZ_);
    meshconv_fused<<<nsm, NT_, SMEM_SZ_>>>(x, gemm, W, bias, out);
}

// round 17
// speedup vs baseline: 1.3862x; 1.3862x over previous
#include <cuda_runtime.h>
#include <stdint.h>

// ---------------- problem constants ----------------
#define B_   8
#define F_   64
#define E_   50000
#define CO_  128
#define KK_  320
#define UE_  64          // edges per pipeline unit (MMA N)
#define NT_  512         // threads per CTA (16 warps)
#define NGW_ 384         // gather threads (warps 0-11)
#define UPB_ 782         // ceil(50000/64)
#define NU_  (UPB_ * B_)
#define NSTEP_ 40        // 320 / 8 (tf32 K per MMA)

#define TMEM_A_  128     // A: cols 128..447; D buffers: 0, 64, 448
#define WS_STR_  324
#define HDR_     4096
#define BUF_     81920   // one G buffer
#define EP_OFF_  (HDR_ + 2 * BUF_)
#define EP_STR_  68
#define SMEM_SZ_ (EP_OFF_ + CO_ * EP_STR_ * 4)   // 202,752 B

// idesc kind::tf32: c=F32, a=TF32, b=TF32, N=64, M=128
#define IDESC64_ 0x8100910u

__device__ __align__(16) float g_xt[(size_t)B_ * E_ * F_];
__device__ int g_idx64;

#if defined(__CUDA_ARCH_FEAT_SM103_ALL)
#define TC_OK_ 1
#else
#define TC_OK_ 0
#endif

// ---------------- PTX helpers (generic) ----------------
__device__ __forceinline__ uint32_t smem_u32(const void* p) {
    uint32_t a;
    asm("{ .reg .u64 t; cvta.to.shared.u64 t, %1; cvt.u32.u64 %0, t; }" : "=r"(a) : "l"(p));
    return a;
}
__device__ __forceinline__ uint32_t elect1() {
    uint32_t p;
    asm volatile("{ .reg .pred p; elect.sync _|p, 0xFFFFFFFF; selp.b32 %0, 1, 0, p; }" : "=r"(p));
    return p;
}
__device__ __forceinline__ float f2t(float x) {
    uint32_t u;
    asm("cvt.rna.tf32.f32 %0, %1;" : "=r"(u) : "f"(x));
    return __uint_as_float(u);
}

#define MB_INIT(mb, c)    asm volatile("mbarrier.init.shared.b64 [%0], %1;" :: "r"(mb), "r"(c) : "memory")
#define MB_INVAL(mb)      asm volatile("mbarrier.inval.shared.b64 [%0];" :: "r"(mb) : "memory")
#define MB_ARRIVE(mb)     asm volatile("mbarrier.arrive.shared.b64 _, [%0];" :: "r"(mb) : "memory")

#define MB_WAIT_PARITY(mb, ph) do {                                          \
    uint32_t _m = (mb), _p = (ph), _d;                                       \
    asm volatile("{ .reg .pred p; mbarrier.try_wait.parity.acquire.cta.shared::cta.b64 p, [%1], %2; selp.b32 %0,1,0,p; }" \
                 : "=r"(_d) : "r"(_m), "r"(_p) : "memory");                  \
    if (!_d) {                                                               \
        asm volatile("{ .reg .pred P1;\n"                                    \
            "WL_%=: mbarrier.try_wait.parity.acquire.cta.shared::cta.b64 P1, [%0], %1, 0x989680;\n" \
            "@P1 bra.uni WD_%=;\n bra.uni WL_%=;\nWD_%=: }"                  \
            :: "r"(_m), "r"(_p) : "memory");                                 \
    } } while (0)

// ---------------- tcgen05 helpers (sm_103a-only) ----------------
#if TC_OK_
#define TC_ALLOC(sa, n)   asm volatile("tcgen05.alloc.cta_group::1.sync.aligned.shared::cta.b32 [%0], %1;" :: "r"(sa), "r"(n) : "memory")
#define TC_RELINQ()       asm volatile("tcgen05.relinquish_alloc_permit.cta_group::1.sync.aligned;")
#define TC_DEALLOC(t, n)  asm volatile("tcgen05.dealloc.cta_group::1.sync.aligned.b32 %0, %1;" :: "r"(t), "r"(n))
#define TC_WAIT_ST()      asm volatile("tcgen05.wait::st.sync.aligned;" ::: "memory")
#define TC_WAIT_LD()      asm volatile("tcgen05.wait::ld.sync.aligned;" ::: "memory")
#define TC_FENCE_BEFORE() asm volatile("tcgen05.fence::before_thread_sync;" ::: "memory")
#define TC_FENCE_AFTER()  asm volatile("tcgen05.fence::after_thread_sync;" ::: "memory")
#define TC_COMMIT(mb)     asm volatile("tcgen05.commit.cta_group::1.mbarrier::arrive::one.shared::cluster.b64 [%0];" :: "r"(mb) : "memory")

#define TC_ST_X32(addr, r) \
    asm volatile("tcgen05.st.sync.aligned.32x32b.x32.b32 [%0], "             \
        "{%1,%2,%3,%4,%5,%6,%7,%8,%9,%10,%11,%12,%13,%14,%15,%16,"          \
        "%17,%18,%19,%20,%21,%22,%23,%24,%25,%26,%27,%28,%29,%30,%31,%32};" \
        :: "r"(addr),                                                        \
        "r"((r)[0]),"r"((r)[1]),"r"((r)[2]),"r"((r)[3]),"r"((r)[4]),"r"((r)[5]),"r"((r)[6]),"r"((r)[7]), \
        "r"((r)[8]),"r"((r)[9]),"r"((r)[10]),"r"((r)[11]),"r"((r)[12]),"r"((r)[13]),"r"((r)[14]),"r"((r)[15]), \
        "r"((r)[16]),"r"((r)[17]),"r"((r)[18]),"r"((r)[19]),"r"((r)[20]),"r"((r)[21]),"r"((r)[22]),"r"((r)[23]), \
        "r"((r)[24]),"r"((r)[25]),"r"((r)[26]),"r"((r)[27]),"r"((r)[28]),"r"((r)[29]),"r"((r)[30]),"r"((r)[31]) \
        : "memory")

#define TC_LD_X16(r, addr) \
    asm volatile("tcgen05.ld.sync.aligned.32x32b.x16.b32 "                   \
        "{%0,%1,%2,%3,%4,%5,%6,%7,%8,%9,%10,%11,%12,%13,%14,%15}, [%16];"    \
        : "=r"((r)[0]),"=r"((r)[1]),"=r"((r)[2]),"=r"((r)[3]),               \
        "=r"((r)[4]),"=r"((r)[5]),"=r"((r)[6]),"=r"((r)[7]),                 \
        "=r"((r)[8]),"=r"((r)[9]),"=r"((r)[10]),"=r"((r)[11]),               \
        "=r"((r)[12]),"=r"((r)[13]),"=r"((r)[14]),"=r"((r)[15])              \
        : "r"(addr))

__device__ __forceinline__ void mma_tf32_ts(uint32_t d, uint32_t a, uint64_t bdesc,
                                            uint32_t idesc, bool acc) {
    uint32_t en = acc ? 1u : 0u;
    asm volatile(
        "{\n\t.reg .pred p;\n\tsetp.ne.u32 p, %5, 0;\n\t"
        "tcgen05.mma.cta_group::1.kind::tf32 [%0], [%1], %2, %3, {%4, %4, %4, %4}, p;\n\t}"
        :: "r"(d), "r"(a), "l"(bdesc), "r"(idesc), "r"(0u), "r"(en) : "memory");
}
#endif // TC_OK_

#define DESC_BASE_ ((2ull << 61) | (1ull << 46) | (64ull << 32) | (1ull << 16))
#define MAKE_DESC(a) (DESC_BASE_ | ((uint64_t)((a) >> 4) & 0x3FFF))
#define SWZ(o) ((o) ^ (((o) >> 3) & 0x70))

// ---------------------------------------------------------------------------
// x (B,F,E) -> xt (B,E,F); block (0,0) also detects gemm dtype.
// ---------------------------------------------------------------------------
__global__ __launch_bounds__(256) void transpose_kernel(const float* __restrict__ x,
                                                        const unsigned int* __restrict__ g) {
    __shared__ float t[64 * 68];
    __shared__ int s_nz;
    int b  = blockIdx.y;
    int e0 = blockIdx.x * 64;
    int tid = threadIdx.x;

    if (blockIdx.x == 0 && blockIdx.y == 0) {
        if (tid == 0) s_nz = 0;
        __syncthreads();
        unsigned acc = 0;
        #pragma unroll
        for (int i = 0; i < 8; i++) acc |= g[(tid + i * 256) * 2 + 1];
        if (acc) atomicOr(&s_nz, 1);
        __syncthreads();
        if (tid == 0) g_idx64 = (s_nz == 0) ? 1 : 0;
        __syncthreads();
    }

    if (e0 + 64 <= E_) {
        #pragma unroll
        for (int i = 0; i < 4; i++) {
            int idx = tid + i * 256;
            int f = idx >> 4, c4 = idx & 15;
            float4 v = *(const float4*)(x + ((size_t)b * F_ + f) * E_ + e0 + c4 * 4);
            *(float4*)(&t[f * 68 + c4 * 4]) = v;
        }
        __syncthreads();
        int e  = tid & 63;
        int jb = tid >> 6;
        float* po = g_xt + ((size_t)b * E_ + e0 + e) * F_;
        #pragma unroll
        for (int jj = 0; jj < 4; jj++) {
            int j = jb + jj * 4;
            float4 v = make_float4(t[(j*4+0)*68 + e], t[(j*4+1)*68 + e],
                                   t[(j*4+2)*68 + e], t[(j*4+3)*68 + e]);
            *(float4*)(po + j * 4) = v;
        }
    } else {
        for (int idx = tid; idx < 64 * 64; idx += 256) {
            int e = e0 + (idx & 63);
            int f = idx >> 6;
            if (e < E_)
                g_xt[((size_t)b * E_ + e) * F_ + f] = x[((size_t)b * F_ + f) * E_ + e];
        }
    }
}

// ---------------------------------------------------------------------------
// Warp-specialized persistent kernel:
//   warps 0-11: gather producers; warp 12: MMA + epilogue; warps 13-15: epilogue.
// mbarriers: sbase+8,+16 = g_full[0..1] (count NGW_); +24,+32,+40 = mma_done[0..2] (count 1).
// ---------------------------------------------------------------------------
#if TC_OK_
__device__ __forceinline__ void do_epilogue(
    int j, int gdim, uint32_t tmem, uint32_t sbase,
    float* ep, float* eprow, float bv, float* __restrict__ out, int tid)
{
    int s = j % 3;
    uint32_t doff = (s == 0) ? 0u : (s == 1) ? 64u : 448u;
    MB_WAIT_PARITY(sbase + 24 + s * 8, (j / 3) & 1);
    TC_FENCE_AFTER();
    #pragma unroll
    for (int q = 0; q < 4; q++) {
        uint32_t r[16];
        TC_LD_X16(r, tmem + doff + q * 16);
        TC_WAIT_LD();
        #pragma unroll
        for (int u = 0; u < 4; u++) {
            float4 w = make_float4(__uint_as_float(r[4*u+0]) + bv,
                                   __uint_as_float(r[4*u+1]) + bv,
                                   __uint_as_float(r[4*u+2]) + bv,
                                   __uint_as_float(r[4*u+3]) + bv);
            *(float4*)(eprow + q * 16 + u * 4) = w;
        }
    }
    TC_FENCE_BEFORE();
    asm volatile("bar.sync 1, 128;" ::: "memory");   // ep filled; D slot free

    int tt = (int)blockIdx.x + j * gdim;
    int jb = tt / UPB_;
    int je0 = (tt - jb * UPB_) * UE_;
    int tloc = tid - NGW_;                            // 0..127
    #pragma unroll
    for (int j4 = 0; j4 < 16; j4++) {
        int idx = tloc + j4 * 128;
        int row = idx >> 4, c4 = idx & 15;
        float4 w = *(const float4*)(ep + row * EP_STR_ + c4 * 4);
        int e = je0 + c4 * 4;
        float* po = out + ((size_t)jb * CO_ + row) * E_ + e;
        if (e + 3 < E_) {
            *(float4*)po = w;
        } else {
            if (e + 0 < E_) po[0] = w.x;
            if (e + 1 < E_) po[1] = w.y;
            if (e + 2 < E_) po[2] = w.z;
            if (e + 3 < E_) po[3] = w.w;
        }
    }
    asm volatile("bar.sync 1, 128;" ::: "memory");   // ep readable done -> reusable
}
#endif

__global__ __launch_bounds__(NT_, 1)
void meshconv_tc(const void*  __restrict__ gemm_raw,
                 const float* __restrict__ Wg,
                 const float* __restrict__ bias,
                 float*       __restrict__ out)
{
#if TC_OK_
    extern __shared__ char smem[];
    uint32_t sbase = smem_u32(smem);
    char*  tile = smem + HDR_;
    float* ep   = (float*)(smem + EP_OFF_);
    uint32_t gsb = sbase + HDR_;

    const int tid = threadIdx.x, wid = tid >> 5, lane = tid & 31;
    const int idx64 = g_idx64;
    const int gdim  = (int)gridDim.x;

    if (wid == 0) {
        TC_ALLOC(sbase, 512);
        TC_RELINQ();
        if (elect1()) {
            MB_INIT(sbase + 8,  NGW_); MB_INIT(sbase + 16, NGW_);
            MB_INIT(sbase + 24, 1); MB_INIT(sbase + 32, 1); MB_INIT(sbase + 40, 1);
        }
    }
    __syncthreads();
    uint32_t tmem;
    asm volatile("ld.shared.b32 %0, [%1];" : "=r"(tmem) : "r"(sbase));

    // ---- stage W: gmem -> smem (kappa = f*5+q -> kappa' = q*64+f) ----
    float* ws = (float*)tile;
    #pragma unroll 4
    for (int i = 0; i < 20; i++) {
        int idx4 = tid + i * NT_;
        int o = idx4 / 80, c4 = idx4 % 80;
        float4 v = *(const float4*)(Wg + o * KK_ + c4 * 4);
        int kk = c4 * 4;
        ws[o * WS_STR_ + ((kk    ) % 5) * 64 + (kk    ) / 5] = v.x;
        ws[o * WS_STR_ + ((kk + 1) % 5) * 64 + (kk + 1) / 5] = v.y;
        ws[o * WS_STR_ + ((kk + 2) % 5) * 64 + (kk + 2) / 5] = v.z;
        ws[o * WS_STR_ + ((kk + 3) % 5) * 64 + (kk + 3) / 5] = v.w;
    }
    __syncthreads();

    // ---- smem -> TMEM (A operand, tf32) ----
    if (tid < 128) {
        const float* wrow = ws + tid * WS_STR_;
        uint32_t woff = (uint32_t)(wid & 3) << 21;
        for (int g = 0; g < 10; g++) {
            uint32_t r[32];
            #pragma unroll
            for (int u = 0; u < 8; u++) {
                float4 v = *(const float4*)(wrow + g * 32 + u * 4);
                asm("cvt.rna.tf32.f32 %0, %1;" : "=r"(r[u*4+0]) : "f"(v.x));
                asm("cvt.rna.tf32.f32 %0, %1;" : "=r"(r[u*4+1]) : "f"(v.y));
                asm("cvt.rna.tf32.f32 %0, %1;" : "=r"(r[u*4+2]) : "f"(v.z));
                asm("cvt.rna.tf32.f32 %0, %1;" : "=r"(r[u*4+3]) : "f"(v.w));
            }
            TC_ST_X32(tmem + TMEM_A_ + g * 32 + woff, r);
            TC_WAIT_ST();
        }
    }
    TC_FENCE_BEFORE();
    __syncthreads();

    const int myU = (NU_ - 1 - (int)blockIdx.x) / gdim + 1;

    if (wid < 12) {
        // ================= gather producers =================
        for (int i = 0; i < myU; i++) {
            int t  = (int)blockIdx.x + i * gdim;
            int b  = t / UPB_;
            int e0 = (t - b * UPB_) * UE_;
            const float* xb = g_xt + (size_t)b * E_ * F_;

            if (i >= 2)
                MB_WAIT_PARITY(sbase + 24 + ((i - 2) % 3) * 8, ((i - 2) / 3) & 1);

            char* buf = tile + (i & 1) * BUF_;

            // tasks: tid, tid+384, (tid<256: tid+768); task = e*16 + c
            #pragma unroll
            for (int k = 0; k < 2; k++) {
                int task = tid + k * NGW_;
                int e = task >> 4, cc = task & 15;
                int eg = e0 + e; if (eg > E_ - 1) eg = E_ - 1;
                int n1, n2, n3, n4;
                if (idx64) {
                    const long long* gp = (const long long*)gemm_raw + ((size_t)b * E_ + eg) * 4;
                    n1 = (int)gp[0]; n2 = (int)gp[1]; n3 = (int)gp[2]; n4 = (int)gp[3];
                } else {
                    int4 gi = *(const int4*)((const int*)gemm_raw + ((size_t)b * E_ + eg) * 4);
                    n1 = gi.x; n2 = gi.y; n3 = gi.z; n4 = gi.w;
                }
                float4 v0 = *((const float4*)(xb + (size_t)eg * F_) + cc);
                float4 v1 = *((const float4*)(xb + (size_t)n1 * F_) + cc);
                float4 v2 = *((const float4*)(xb + (size_t)n2 * F_) + cc);
                float4 v3 = *((const float4*)(xb + (size_t)n3 * F_) + cc);
                float4 v4 = *((const float4*)(xb + (size_t)n4 * F_) + cc);

                float4 w0 = make_float4(f2t(v0.x), f2t(v0.y), f2t(v0.z), f2t(v0.w));
                float4 w1 = make_float4(f2t(v1.x+v3.x), f2t(v1.y+v3.y), f2t(v1.z+v3.z), f2t(v1.w+v3.w));
                float4 w2 = make_float4(f2t(v2.x+v4.x), f2t(v2.y+v4.y), f2t(v2.z+v4.z), f2t(v2.w+v4.w));
                float4 w3 = make_float4(f2t(fabsf(v1.x-v3.x)), f2t(fabsf(v1.y-v3.y)),
                                        f2t(fabsf(v1.z-v3.z)), f2t(fabsf(v1.w-v3.w)));
                float4 w4 = make_float4(f2t(fabsf(v2.x-v4.x)), f2t(fabsf(v2.y-v4.y)),
                                        f2t(fabsf(v2.z-v4.z)), f2t(fabsf(v2.w-v4.w)));

                int half = cc >> 3;
                uint32_t sb = SWZ(((uint32_t)(e >> 3) << 10) + ((uint32_t)(e & 7) << 7)
                                  + ((uint32_t)(cc & 7) << 4));
                *(float4*)(buf + sb + (uint32_t)((0 + half) << 13)) = w0;
                *(float4*)(buf + sb + (uint32_t)((2 + half) << 13)) = w1;
                *(float4*)(buf + sb + (uint32_t)((4 + half) << 13)) = w2;
                *(float4*)(buf + sb + (uint32_t)((6 + half) << 13)) = w3;
                *(float4*)(buf + sb + (uint32_t)((8 + half) << 13)) = w4;
            }
            if (tid < 256) {
                int task = tid + 2 * NGW_;
                int e = task >> 4, cc = task & 15;
                int eg = e0 + e; if (eg > E_ - 1) eg = E_ - 1;
                int n1, n2, n3, n4;
                if (idx64) {
                    const long long* gp = (const long long*)gemm_raw + ((size_t)b * E_ + eg) * 4;
                    n1 = (int)gp[0]; n2 = (int)gp[1]; n3 = (int)gp[2]; n4 = (int)gp[3];
                } else {
                    int4 gi = *(const int4*)((const int*)gemm_raw + ((size_t)b * E_ + eg) * 4);
                    n1 = gi.x; n2 = gi.y; n3 = gi.z; n4 = gi.w;
                }
                float4 v0 = *((const float4*)(xb + (size_t)eg * F_) + cc);
                float4 v1 = *((const float4*)(xb + (size_t)n1 * F_) + cc);
                float4 v2 = *((const float4*)(xb + (size_t)n2 * F_) + cc);
                float4 v3 = *((const float4*)(xb + (size_t)n3 * F_) + cc);
                float4 v4 = *((const float4*)(xb + (size_t)n4 * F_) + cc);

                float4 w0 = make_float4(f2t(v0.x), f2t(v0.y), f2t(v0.z), f2t(v0.w));
                float4 w1 = make_float4(f2t(v1.x+v3.x), f2t(v1.y+v3.y), f2t(v1.z+v3.z), f2t(v1.w+v3.w));
                float4 w2 = make_float4(f2t(v2.x+v4.x), f2t(v2.y+v4.y), f2t(v2.z+v4.z), f2t(v2.w+v4.w));
                float4 w3 = make_float4(f2t(fabsf(v1.x-v3.x)), f2t(fabsf(v1.y-v3.y)),
                                        f2t(fabsf(v1.z-v3.z)), f2t(fabsf(v1.w-v3.w)));
                float4 w4 = make_float4(f2t(fabsf(v2.x-v4.x)), f2t(fabsf(v2.y-v4.y)),
                                        f2t(fabsf(v2.z-v4.z)), f2t(fabsf(v2.w-v4.w)));

                int half = cc >> 3;
                uint32_t sb = SWZ(((uint32_t)(e >> 3) << 10) + ((uint32_t)(e & 7) << 7)
                                  + ((uint32_t)(cc & 7) << 4));
                *(float4*)(buf + sb + (uint32_t)((0 + half) << 13)) = w0;
                *(float4*)(buf + sb + (uint32_t)((2 + half) << 13)) = w1;
                *(float4*)(buf + sb + (uint32_t)((4 + half) << 13)) = w2;
                *(float4*)(buf + sb + (uint32_t)((6 + half) << 13)) = w3;
                *(float4*)(buf + sb + (uint32_t)((8 + half) << 13)) = w4;
            }
            asm volatile("fence.proxy.async.shared::cta;" ::: "memory");
            MB_ARRIVE(sbase + 8 + (i & 1) * 8);
        }
    } else {
        // ================= MMA + epilogue consumers =================
        const int g16u = 0; (void)g16u;
        const int orow = (wid & 3) * 32 + lane;
        const float bv = __ldg(bias + orow);
        float* eprow = ep + orow * EP_STR_;

        if (wid == 12) {
            for (int i = 0; i < myU; i++) {
                MB_WAIT_PARITY(sbase + 8 + (i & 1) * 8, (i / 2) & 1);
                TC_FENCE_AFTER();
                if (elect1()) {
                    int s = i % 3;
                    uint32_t doff = (s == 0) ? 0u : (s == 1) ? 64u : 448u;
                    uint64_t bb = MAKE_DESC(gsb + (uint32_t)(i & 1) * BUF_);
                    #pragma unroll 1
                    for (int k = 0; k < NSTEP_; k++) {
                        uint64_t bd = bb + (uint64_t)((k >> 2) * 512 + (k & 3) * 2);
                        mma_tf32_ts(tmem + doff, tmem + TMEM_A_ + k * 8, bd, IDESC64_, k > 0);
                    }
                    TC_COMMIT(sbase + 24 + s * 8);
                }
                __syncwarp();
                if (i >= 2) do_epilogue(i - 2, gdim, tmem, sbase, ep, eprow, bv, out, tid);
            }
            if (myU >= 2) do_epilogue(myU - 2, gdim, tmem, sbase, ep, eprow, bv, out, tid);
            if (myU >= 1) do_epilogue(myU - 1, gdim, tmem, sbase, ep, eprow, bv, out, tid);
        } else {
            for (int j = 0; j < myU; j++)
                do_epilogue(j, gdim, tmem, sbase, ep, eprow, bv, out, tid);
        }
    }

    // ---- cleanup ----
    __syncthreads();
    if (wid == 0) {
        if (elect1()) {
            MB_INVAL(sbase + 8); MB_INVAL(sbase + 16);
            MB_INVAL(sbase + 24); MB_INVAL(sbase + 32); MB_INVAL(sbase + 40);
        }
        TC_DEALLOC(tmem, 512);
    }
#endif // TC_OK_
}

// ---------------------------------------------------------------------------
extern "C" void kernel_launch(void* const* d_in, const int* in_sizes, int n_in,
                              void* d_out, int out_size) {
    const float* x    = (const float*)d_in[0];
    const void*  gemm = d_in[1];
    const float* W    = (const float*)d_in[2];
    const float* bias = (const float*)d_in[3];
    float*       out  = (float*)d_out;

    dim3 tg((E_ + 63) / 64, B_);
    transpose_kernel<<<tg, 256>>>(x, (const unsigned int*)gemm);

    int dev = 0, nsm = 148;
    cudaGetDevice(&dev);
    cudaDeviceGetAttribute(&nsm, cudaDevAttrMultiProcessorCount, dev);
    if (nsm <= 0) nsm = 148;

    cudaFuncSetAttribute(meshconv_tc,
                         cudaFuncAttributeMaxDynamicSharedMemorySize, SMEM_SZ_);
    meshconv_tc<<<nsm, NT_, SMEM_SZ_>>>(gemm, W, bias, out);
}